// round 9
// baseline (speedup 1.0000x reference)
#include <cuda_runtime.h>
#include <cuda_fp16.h>
#include <cstdint>
#include <math.h>

// Problem dims (fixed by the dataset)
#define Bc 256
#define Nc 4096
#define Mc 16384
#define STEPS 50

// ---------------------------------------------------------------------------
// Device-global scratch
// ---------------------------------------------------------------------------
__device__ __half g_Wh[(size_t)Mc * Nc];    // W fp16 [m][n] (both GEMMs)
__device__ __half g_sh[(size_t)Bc * Nc];    // state fp16 [b][n]
__device__ __half g_fh[(size_t)Bc * Mc];    // e = exp(beta*h) fp16 [b][m]
__device__ float  g_fsumP[2][Bc];           // parity-buffered row sums
__device__ float  g_norm[STEPS];

__device__ unsigned g_cnt_bar;
__device__ volatile unsigned g_gen_bar;

// ---------------------------------------------------------------------------
// PTX helpers (sm_80-era, legal on plain sm_103)
// ---------------------------------------------------------------------------
__device__ __forceinline__ uint32_t s2u(const void* p) {
    return (uint32_t)__cvta_generic_to_shared(p);
}
__device__ __forceinline__ void cpa16(uint32_t dst, const void* src) {
    asm volatile("cp.async.cg.shared.global [%0], [%1], 16;" :: "r"(dst), "l"(src));
}
#define CP_COMMIT() asm volatile("cp.async.commit_group;" ::: "memory")
#define CP_WAIT(n)  asm volatile("cp.async.wait_group %0;" :: "n"(n) : "memory")

__device__ __forceinline__ void ldm4(uint32_t* r, uint32_t addr) {
    asm volatile("ldmatrix.sync.aligned.m8n8.x4.shared.b16 {%0,%1,%2,%3}, [%4];"
                 : "=r"(r[0]), "=r"(r[1]), "=r"(r[2]), "=r"(r[3]) : "r"(addr));
}
__device__ __forceinline__ void ldm4t(uint32_t* r, uint32_t addr) {
    asm volatile("ldmatrix.sync.aligned.m8n8.x4.trans.shared.b16 {%0,%1,%2,%3}, [%4];"
                 : "=r"(r[0]), "=r"(r[1]), "=r"(r[2]), "=r"(r[3]) : "r"(addr));
}
__device__ __forceinline__ void mma16816(float* d, const uint32_t* a,
                                         uint32_t b0, uint32_t b1) {
    asm volatile(
        "mma.sync.aligned.m16n8k16.row.col.f32.f16.f16.f32 "
        "{%0,%1,%2,%3}, {%4,%5,%6,%7}, {%8,%9}, {%0,%1,%2,%3};"
        : "+f"(d[0]), "+f"(d[1]), "+f"(d[2]), "+f"(d[3])
        : "r"(a[0]), "r"(a[1]), "r"(a[2]), "r"(a[3]), "r"(b0), "r"(b1));
}

// ---------------------------------------------------------------------------
// Software global barrier (grid == #SMs, 1 CTA/SM -> co-resident)
// ---------------------------------------------------------------------------
__device__ __forceinline__ void gbar(int G) {
    __syncthreads();
    if (threadIdx.x == 0) {
        __threadfence();
        unsigned my = g_gen_bar;
        unsigned old = atomicAdd(&g_cnt_bar, 1u);
        if (old == (unsigned)G - 1u) {
            g_cnt_bar = 0u;
            __threadfence();
            g_gen_bar = my + 1u;
        } else {
            while (g_gen_bar == my) __nanosleep(64);
        }
        __threadfence();
    }
    __syncthreads();
}

// ---------------------------------------------------------------------------
// Init
// ---------------------------------------------------------------------------
__global__ void k_init(const float* __restrict__ inp, float* __restrict__ state) {
    int i = blockIdx.x * blockDim.x + threadIdx.x;
    if (i < Bc * Nc) {
        float x = inp[i];
        state[i] = x;
        g_sh[i] = __float2half(x);
    }
    if (i < STEPS) g_norm[i] = 0.0f;
    if (i < Bc) { g_fsumP[0][i] = 0.0f; g_fsumP[1][i] = 0.0f; }
}

// ---------------------------------------------------------------------------
// W -> fp16 (elementwise)
// ---------------------------------------------------------------------------
__global__ void __launch_bounds__(256) k_convW(const float* __restrict__ W) {
    size_t i = (size_t)blockIdx.x * 1024 + threadIdx.x * 4;
    float4 v = *(const float4*)(W + i);
    *(__half2*)(g_Wh + i)     = __floats2half2_rn(v.x, v.y);
    *(__half2*)(g_Wh + i + 2) = __floats2half2_rn(v.z, v.w);
}

// ---------------------------------------------------------------------------
// GEMM tiles (fragment double-buffered, 3-stage cp.async, one sync/chunk)
// MODE 0: h-GEMM, 128(b)x128(m), K=4096. Warps 4x4, 32x32 each.
//         Epilogue: e = exp(beta*acc) -> g_fh + row-sum atomics.
// MODE 1: v-GEMM, 64(b)x128(n), K=16384 full. Warps 2x8, 32x16 each.
//         Epilogue: FUSED state update + norm (v = u / rowsum).
// ---------------------------------------------------------------------------
#define KCH    64
#define ROWB   144                 // K-major row stride: 128B data + 16B pad
#define ATILE0 (128 * ROWB)        // 18432 B
#define STG0   (2 * ATILE0)        // 36864 B
#define ATILE1 (64 * ROWB)         // 9216 B
#define STG1   (ATILE1 + 64 * 256) // 25600 B
#define NSTG   3
#define SMEM_T (NSTG * STG0)       // 110592 B

template <int MODE>
__device__ __forceinline__ void load_stage(uint32_t sbase, int tid,
                                           const __half* A, const __half* B, int ch) {
    if (MODE == 0) {
#pragma unroll
        for (int t2 = 0; t2 < 2; t2++) {
            int idx = tid + t2 * 512;
            int r = idx >> 3, q = idx & 7;
            uint32_t so = (uint32_t)(r * ROWB + q * 16);
            cpa16(sbase + so, A + (size_t)r * Nc + ch * KCH + q * 8);
            cpa16(sbase + ATILE0 + so, B + (size_t)r * Nc + ch * KCH + q * 8);
        }
    } else {
        {   // A: 64 rows x 8 segs (one per thread)
            int r = tid >> 3, q = tid & 7;
            cpa16(sbase + (uint32_t)(r * ROWB + q * 16),
                  A + (size_t)r * Mc + ch * KCH + q * 8);
        }
#pragma unroll
        for (int t2 = 0; t2 < 2; t2++) {   // B: 64 k-rows x 16 segs, XOR swizzle
            int idx = tid + t2 * 512;
            int r = idx >> 4, q = idx & 15;
            cpa16(sbase + ATILE1 + (uint32_t)(r * 256 + ((q ^ (r & 7)) * 16)),
                  B + (size_t)(ch * KCH + r) * Nc + q * 8);
        }
    }
}

template <int MODE>
__device__ __forceinline__ void load_frags(uint32_t cur, int ks,
        uint32_t (&aF)[2][4], uint32_t (&bF)[2][4],
        int rw, int cw, int lrow, int lkb, int kr, int nseg, int lid) {
#pragma unroll
    for (int sub = 0; sub < 2; ++sub) {
        uint32_t ra = (uint32_t)((rw * 32 + sub * 16 + lrow) * ROWB + ks * 32 + lkb);
        ldm4(aF[sub], cur + ra);
    }
    if (MODE) {
        uint32_t rb = (uint32_t)((ks * 16 + kr) * 256 + ((nseg ^ (lid & 7)) * 16));
        ldm4t(bF[0], cur + ATILE1 + rb);
    } else {
#pragma unroll
        for (int cg = 0; cg < 2; ++cg) {
            uint32_t rb = (uint32_t)((cw * 32 + cg * 16 + lrow) * ROWB + ks * 32 + lkb);
            ldm4(bF[cg], cur + ATILE0 + rb);
        }
    }
}

template <int MODE>
__device__ void gemm_tile(char* smem, int t, float beta,
                          float* fsumA, const float* fsumR,
                          float invtau, float* state, int step) {
    const int tid = threadIdx.x;
    const int wid = tid >> 5;
    const int lid = tid & 31;
    const int rw  = MODE ? (wid & 1) : (wid & 3);
    const int cw  = MODE ? (wid >> 1) : (wid >> 2);
    const uint32_t sb = s2u(smem);

    constexpr int NCH = MODE ? 256 : 64;
    constexpr uint32_t STG = MODE ? STG1 : STG0;

    const int b0 = MODE ? (t & 3) * 64 : (t & 1) * 128;
    const int c0 = MODE ? (t >> 2) * 128 : (t >> 1) * 128;

    const __half* Ap = MODE ? (g_fh + (size_t)b0 * Mc) : (g_sh + (size_t)b0 * Nc);
    const __half* Bp = MODE ? (g_Wh + c0) : (g_Wh + (size_t)c0 * Nc);

    float acc[2][4][4];
#pragma unroll
    for (int i = 0; i < 2; i++)
#pragma unroll
        for (int j = 0; j < 4; j++)
#pragma unroll
            for (int v = 0; v < 4; v++) acc[i][j][v] = 0.0f;

    const int lrow = ((lid >> 3) & 1) * 8 + (lid & 7);
    const int lkb  = (lid >> 4) * 16;
    const int kr   = ((lid >> 4) & 1) * 8 + (lid & 7);
    const int nseg = cw * 2 + ((lid >> 3) & 1);

    load_stage<MODE>(sb + 0 * STG, tid, Ap, Bp, 0);
    CP_COMMIT();
    load_stage<MODE>(sb + 1 * STG, tid, Ap, Bp, 1);
    CP_COMMIT();

    uint32_t aF[2][2][4];
    uint32_t bF[2][2][4];

    for (int ch = 0; ch < NCH; ++ch) {
        const uint32_t cur = sb + (uint32_t)(ch % NSTG) * STG;
        if (ch + 2 < NCH) { CP_WAIT(1); } else { CP_WAIT(0); }
        __syncthreads();

        // ks0 fragments first, then the next-stage bulk load (keeps the LSU
        // burst out of the critical LDSM->MMA path)
        load_frags<MODE>(cur, 0, aF[0], bF[0], rw, cw, lrow, lkb, kr, nseg, lid);
        if (ch + 2 < NCH) {
            load_stage<MODE>(sb + (uint32_t)((ch + 2) % NSTG) * STG, tid,
                             Ap, Bp, ch + 2);
            CP_COMMIT();
        }

#pragma unroll
        for (int ks = 0; ks < 4; ++ks) {
            const int buf = ks & 1;
            if (ks < 3)
                load_frags<MODE>(cur, ks + 1, aF[buf ^ 1], bF[buf ^ 1],
                                 rw, cw, lrow, lkb, kr, nseg, lid);
#pragma unroll
            for (int sub = 0; sub < 2; ++sub) {
                if (MODE) {
#pragma unroll
                    for (int hf = 0; hf < 2; ++hf)
                        mma16816(acc[sub][hf], aF[buf][sub],
                                 bF[buf][0][hf], bF[buf][0][hf + 2]);
                } else {
#pragma unroll
                    for (int cg = 0; cg < 2; ++cg)
#pragma unroll
                        for (int hf = 0; hf < 2; ++hf)
                            mma16816(acc[sub][cg * 2 + hf], aF[buf][sub],
                                     bF[buf][cg][hf], bF[buf][cg][hf + 2]);
                }
            }
        }
    }
    __syncthreads();   // stages dead; smem reusable in epilogue

    const int gr = lid >> 2;
    const int gc = (lid & 3) * 2;

    if (MODE == 0) {
        // Epilogue: e = exp(beta*h) -> fp16 g_fh; row-sum reduction
        float* rsum = (float*)smem;
        if (tid < 128) rsum[tid] = 0.0f;
        __syncthreads();

#pragma unroll
        for (int sub = 0; sub < 2; ++sub) {
            const int rbase = b0 + rw * 32 + sub * 16 + gr;
            float s0 = 0.0f, s1 = 0.0f;
#pragma unroll
            for (int nt = 0; nt < 4; ++nt) {
                float e0 = expf(beta * acc[sub][nt][0]);
                float e1 = expf(beta * acc[sub][nt][1]);
                float e2 = expf(beta * acc[sub][nt][2]);
                float e3 = expf(beta * acc[sub][nt][3]);
                const int col = c0 + cw * 32 + nt * 8 + gc;
                *(__half2*)(g_fh + (size_t)rbase * Mc + col) =
                    __floats2half2_rn(e0, e1);
                *(__half2*)(g_fh + (size_t)(rbase + 8) * Mc + col) =
                    __floats2half2_rn(e2, e3);
                s0 += e0 + e1;
                s1 += e2 + e3;
            }
            s0 += __shfl_xor_sync(0xFFFFFFFF, s0, 1);
            s0 += __shfl_xor_sync(0xFFFFFFFF, s0, 2);
            s1 += __shfl_xor_sync(0xFFFFFFFF, s1, 1);
            s1 += __shfl_xor_sync(0xFFFFFFFF, s1, 2);
            if ((lid & 3) == 0) {
                atomicAdd(&rsum[rw * 32 + sub * 16 + gr], s0);
                atomicAdd(&rsum[rw * 32 + sub * 16 + gr + 8], s1);
            }
        }
        __syncthreads();
        if (tid < 128) atomicAdd(&fsumA[b0 + tid], rsum[tid]);
        __syncthreads();
    } else {
        // FUSED epilogue: v = u / rowsum; state update; norm accumulation
        float sumsq = 0.0f;
#pragma unroll
        for (int sub = 0; sub < 2; ++sub) {
            const int r0 = b0 + rw * 32 + sub * 16 + gr;
            const float inv0 = 1.0f / fsumR[r0];
            const float inv1 = 1.0f / fsumR[r0 + 8];
#pragma unroll
            for (int nt = 0; nt < 2; ++nt) {
                const int col = c0 + cw * 16 + nt * 8 + gc;
                size_t i0 = (size_t)r0 * Nc + col;
                size_t i1 = (size_t)(r0 + 8) * Nc + col;
                float v0 = acc[sub][nt][0] * inv0;
                float v1 = acc[sub][nt][1] * inv0;
                float v2 = acc[sub][nt][2] * inv1;
                float v3 = acc[sub][nt][3] * inv1;
                float2 s01 = *(float2*)(state + i0);
                float2 s23 = *(float2*)(state + i1);
                float n0 = s01.x + invtau * (v0 - s01.x);
                float n1 = s01.y + invtau * (v1 - s01.y);
                float n2 = s23.x + invtau * (v2 - s23.x);
                float n3 = s23.y + invtau * (v3 - s23.y);
                float d0 = n0 - s01.x, d1 = n1 - s01.y;
                float d2 = n2 - s23.x, d3 = n3 - s23.y;
                sumsq += d0 * d0 + d1 * d1 + d2 * d2 + d3 * d3;
                *(float2*)(state + i0) = make_float2(n0, n1);
                *(float2*)(state + i1) = make_float2(n2, n3);
                *(__half2*)(g_sh + i0) = __floats2half2_rn(n0, n1);
                *(__half2*)(g_sh + i1) = __floats2half2_rn(n2, n3);
            }
        }
#pragma unroll
        for (int o = 16; o > 0; o >>= 1)
            sumsq += __shfl_xor_sync(0xFFFFFFFF, sumsq, o);
        float* red = (float*)smem;
        if (tid == 0) red[0] = 0.0f;
        __syncthreads();
        if (lid == 0) atomicAdd(&red[0], sumsq);
        __syncthreads();
        if (tid == 0) atomicAdd(&g_norm[step], red[0]);
        __syncthreads();
    }
}

// ---------------------------------------------------------------------------
// Persistent kernel: all steps + device-side convergence freeze
// ---------------------------------------------------------------------------
__global__ void __launch_bounds__(512, 1) k_steps(float* __restrict__ state,
                                                  const float* __restrict__ beta_p,
                                                  const float* __restrict__ tau_p,
                                                  int G) {
    extern __shared__ char smem[];
    const int tid = threadIdx.x;
    const float beta = *beta_p;
    const float invtau = 1.0f / (*tau_p);

    for (int step = 0; step < STEPS; ++step) {
        float* fsumA = g_fsumP[step & 1];
        // zero the OTHER parity buffer (its readers finished 2 gbars ago;
        // its next writers start 2 gbars from now)
        if (blockIdx.x == 0 && tid < Bc) g_fsumP[(step + 1) & 1][tid] = 0.0f;

        // GEMM1 + fused exp/rowsum (256 tiles)
        for (int t = blockIdx.x; t < 256; t += G)
            gemm_tile<0>(smem, t, beta, fsumA, nullptr, 0.0f, nullptr, step);
        gbar(G);

        // GEMM2 full-K + fused update/norm (128 tiles)
        for (int t = blockIdx.x; t < 128; t += G)
            gemm_tile<1>(smem, t, beta, nullptr, fsumA, invtau, state, step);
        gbar(G);

        float nrm = *(volatile float*)&g_norm[step];
        if (sqrtf(nrm) <= 1e-3f) break;
        __syncthreads();
    }
}

// ---------------------------------------------------------------------------
// kernel_launch
// ---------------------------------------------------------------------------
extern "C" void kernel_launch(void* const* d_in, const int* in_sizes, int n_in,
                              void* d_out, int out_size) {
    const float* inp  = (const float*)d_in[0];
    const float* W    = (const float*)d_in[1];
    const float* beta = (const float*)d_in[2];
    const float* tau  = (const float*)d_in[3];
    float* state = (float*)d_out;

    int dev = 0;
    cudaGetDevice(&dev);
    cudaDeviceProp props;
    cudaGetDeviceProperties(&props, dev);
    const int G = props.multiProcessorCount;

    cudaFuncSetAttribute(k_steps, cudaFuncAttributeMaxDynamicSharedMemorySize, SMEM_T);

    k_init<<<(Bc * Nc + 255) / 256, 256>>>(inp, state);
    k_convW<<<(size_t)Mc * Nc / 1024, 256>>>(W);
    k_steps<<<G, 512, SMEM_T>>>(state, beta, tau, G);
}

// round 10
// speedup vs baseline: 1.0790x; 1.0790x over previous
#include <cuda_runtime.h>
#include <cuda_fp16.h>
#include <cstdint>
#include <math.h>

// Problem dims (fixed by the dataset)
#define Bc 256
#define Nc 4096
#define Mc 16384
#define STEPS 50

// ---------------------------------------------------------------------------
// Device-global scratch
// ---------------------------------------------------------------------------
__device__ __half g_Wh[(size_t)Mc * Nc];    // W fp16 [m][n] (both GEMMs)
__device__ __half g_sh[(size_t)Bc * Nc];    // state fp16 [b][n]
__device__ __half g_fh[(size_t)Bc * Mc];    // e = exp(beta*h) fp16 [b][m]
__device__ float  g_fsum [Bc];              // row sums (accumulating)
__device__ float  g_fsum2[Bc];              // snapshot read by update
__device__ float  g_vpart[2][(size_t)Bc * Nc];
__device__ float  g_norm[STEPS];

__device__ unsigned g_cnt_bar;
__device__ volatile unsigned g_gen_bar;

// ---------------------------------------------------------------------------
// PTX helpers (sm_80-era, legal on plain sm_103)
// ---------------------------------------------------------------------------
__device__ __forceinline__ uint32_t s2u(const void* p) {
    return (uint32_t)__cvta_generic_to_shared(p);
}
__device__ __forceinline__ void cpa16(uint32_t dst, const void* src) {
    asm volatile("cp.async.cg.shared.global [%0], [%1], 16;" :: "r"(dst), "l"(src));
}
#define CP_COMMIT() asm volatile("cp.async.commit_group;" ::: "memory")
#define CP_WAIT(n)  asm volatile("cp.async.wait_group %0;" :: "n"(n) : "memory")

__device__ __forceinline__ void ldm4(uint32_t* r, uint32_t addr) {
    asm volatile("ldmatrix.sync.aligned.m8n8.x4.shared.b16 {%0,%1,%2,%3}, [%4];"
                 : "=r"(r[0]), "=r"(r[1]), "=r"(r[2]), "=r"(r[3]) : "r"(addr));
}
__device__ __forceinline__ void ldm4t(uint32_t* r, uint32_t addr) {
    asm volatile("ldmatrix.sync.aligned.m8n8.x4.trans.shared.b16 {%0,%1,%2,%3}, [%4];"
                 : "=r"(r[0]), "=r"(r[1]), "=r"(r[2]), "=r"(r[3]) : "r"(addr));
}
__device__ __forceinline__ void mma16816(float* d, const uint32_t* a,
                                         uint32_t b0, uint32_t b1) {
    asm volatile(
        "mma.sync.aligned.m16n8k16.row.col.f32.f16.f16.f32 "
        "{%0,%1,%2,%3}, {%4,%5,%6,%7}, {%8,%9}, {%0,%1,%2,%3};"
        : "+f"(d[0]), "+f"(d[1]), "+f"(d[2]), "+f"(d[3])
        : "r"(a[0]), "r"(a[1]), "r"(a[2]), "r"(a[3]), "r"(b0), "r"(b1));
}

// ---------------------------------------------------------------------------
// Software global barrier (grid == #SMs, 1 CTA/SM -> co-resident)
// ---------------------------------------------------------------------------
__device__ __forceinline__ void gbar(int G) {
    __syncthreads();
    if (threadIdx.x == 0) {
        __threadfence();
        unsigned my = g_gen_bar;
        unsigned old = atomicAdd(&g_cnt_bar, 1u);
        if (old == (unsigned)G - 1u) {
            g_cnt_bar = 0u;
            __threadfence();
            g_gen_bar = my + 1u;
        } else {
            while (g_gen_bar == my) __nanosleep(64);
        }
        __threadfence();
    }
    __syncthreads();
}

// ---------------------------------------------------------------------------
// Init
// ---------------------------------------------------------------------------
__global__ void k_init(const float* __restrict__ inp, float* __restrict__ state) {
    int i = blockIdx.x * blockDim.x + threadIdx.x;
    if (i < Bc * Nc) {
        float x = inp[i];
        state[i] = x;
        g_sh[i] = __float2half(x);
    }
    if (i < STEPS) g_norm[i] = 0.0f;
    if (i < Bc) { g_fsum[i] = 0.0f; g_fsum2[i] = 0.0f; }
}

// ---------------------------------------------------------------------------
// W -> fp16 (elementwise)
// ---------------------------------------------------------------------------
__global__ void __launch_bounds__(256) k_convW(const float* __restrict__ W) {
    size_t i = (size_t)blockIdx.x * 1024 + threadIdx.x * 4;
    float4 v = *(const float4*)(W + i);
    *(__half2*)(g_Wh + i)     = __floats2half2_rn(v.x, v.y);
    *(__half2*)(g_Wh + i + 2) = __floats2half2_rn(v.z, v.w);
}

// ---------------------------------------------------------------------------
// Shared sizes
// ---------------------------------------------------------------------------
#define KCH    64
#define ROWB   144                   // K-major row stride (128B + 16B pad)
// GEMM1: 256(b) x 128(m), 2-stage.  Stage = A(256 rows) + B(128 rows)
#define A1_T   (256 * ROWB)          // 36864 B
#define STG1   (A1_T + 128 * ROWB)   // 55296 B
// GEMM2: 128(b) x 128(n), z-split 2, 3-stage (R8 proven layout)
#define A2_T   (128 * ROWB)          // 18432 B
#define STG2   (2 * A2_T)            // 36864 B
#define SMEM_T (2 * STG1)            // 110592 B ( == 3*STG2 )

// ---------------------------------------------------------------------------
// GEMM1 tile: C[256(b) x 128(m)] = state[b][k] * W[m][k], K=4096.
// 16 warps 4(b) x 4(m), warp tile 64x32. 2-stage cp.async, 1 sync/chunk.
// Epilogue: e = __expf(beta*acc) -> g_fh + row-sum atomics into g_fsum.
// ---------------------------------------------------------------------------
__device__ __forceinline__ void load_g1(uint32_t sbase, int tid,
                                        const __half* Bp, int ch) {
#pragma unroll
    for (int t2 = 0; t2 < 4; t2++) {           // A: 256 rows x 8 segs
        int idx = tid + t2 * 512;              // 0..2047
        int r = idx >> 3, q = idx & 7;
        cpa16(sbase + (uint32_t)(r * ROWB + q * 16),
              g_sh + (size_t)r * Nc + ch * KCH + q * 8);
    }
#pragma unroll
    for (int t2 = 0; t2 < 2; t2++) {           // B: 128 rows x 8 segs
        int idx = tid + t2 * 512;              // 0..1023
        int r = idx >> 3, q = idx & 7;
        cpa16(sbase + A1_T + (uint32_t)(r * ROWB + q * 16),
              Bp + (size_t)r * Nc + ch * KCH + q * 8);
    }
}

__device__ void g1_tile(char* smem, int t, float beta) {
    const int tid = threadIdx.x;
    const int wid = tid >> 5;
    const int lid = tid & 31;
    const int rw  = wid & 3;            // warp b-row: 64 rows
    const int cw  = wid >> 2;           // warp m-col: 32 cols
    const uint32_t sb = s2u(smem);

    const int c0 = t * 128;
    const __half* Bp = g_Wh + (size_t)c0 * Nc;

    float acc[4][4][4];
#pragma unroll
    for (int i = 0; i < 4; i++)
#pragma unroll
        for (int j = 0; j < 4; j++)
#pragma unroll
            for (int v = 0; v < 4; v++) acc[i][j][v] = 0.0f;

    const int lrow = ((lid >> 3) & 1) * 8 + (lid & 7);
    const int lkb  = (lid >> 4) * 16;

    load_g1(sb, tid, Bp, 0);
    CP_COMMIT();

    for (int ch = 0; ch < 64; ++ch) {
        const uint32_t cur = sb + (uint32_t)(ch & 1) * STG1;
        CP_WAIT(0);
        __syncthreads();
        if (ch + 1 < 64) {
            load_g1(sb + (uint32_t)((ch + 1) & 1) * STG1, tid, Bp, ch + 1);
            CP_COMMIT();
        }

#pragma unroll
        for (int ks = 0; ks < 4; ++ks) {
            uint32_t aF[4][4];
            uint32_t bF[2][4];
#pragma unroll
            for (int sub = 0; sub < 4; ++sub) {
                uint32_t ra = (uint32_t)((rw * 64 + sub * 16 + lrow) * ROWB
                                         + ks * 32 + lkb);
                ldm4(aF[sub], cur + ra);
            }
#pragma unroll
            for (int cg = 0; cg < 2; ++cg) {
                uint32_t rb = (uint32_t)((cw * 32 + cg * 16 + lrow) * ROWB
                                         + ks * 32 + lkb);
                ldm4(bF[cg], cur + A1_T + rb);
            }
#pragma unroll
            for (int sub = 0; sub < 4; ++sub)
#pragma unroll
                for (int cg = 0; cg < 2; ++cg)
#pragma unroll
                    for (int hf = 0; hf < 2; ++hf)
                        mma16816(acc[sub][cg * 2 + hf], aF[sub],
                                 bF[cg][hf], bF[cg][hf + 2]);
        }
    }
    __syncthreads();   // stages dead; smem reusable

    // Epilogue: e = __expf(beta*h) -> fp16 g_fh; row sums -> g_fsum
    const int gr = lid >> 2;
    const int gc = (lid & 3) * 2;
    float* rsum = (float*)smem;
    if (tid < 256) rsum[tid] = 0.0f;
    __syncthreads();

#pragma unroll
    for (int sub = 0; sub < 4; ++sub) {
        const int rbase = rw * 64 + sub * 16 + gr;
        float s0 = 0.0f, s1 = 0.0f;
#pragma unroll
        for (int nt = 0; nt < 4; ++nt) {
            float e0 = __expf(beta * acc[sub][nt][0]);
            float e1 = __expf(beta * acc[sub][nt][1]);
            float e2 = __expf(beta * acc[sub][nt][2]);
            float e3 = __expf(beta * acc[sub][nt][3]);
            const int col = c0 + cw * 32 + nt * 8 + gc;
            *(__half2*)(g_fh + (size_t)rbase * Mc + col) =
                __floats2half2_rn(e0, e1);
            *(__half2*)(g_fh + (size_t)(rbase + 8) * Mc + col) =
                __floats2half2_rn(e2, e3);
            s0 += e0 + e1;
            s1 += e2 + e3;
        }
        s0 += __shfl_xor_sync(0xFFFFFFFF, s0, 1);
        s0 += __shfl_xor_sync(0xFFFFFFFF, s0, 2);
        s1 += __shfl_xor_sync(0xFFFFFFFF, s1, 1);
        s1 += __shfl_xor_sync(0xFFFFFFFF, s1, 2);
        if ((lid & 3) == 0) {
            atomicAdd(&rsum[rbase], s0);
            atomicAdd(&rsum[rbase + 8], s1);
        }
    }
    __syncthreads();
    if (tid < 256) atomicAdd(&g_fsum[tid], rsum[tid]);
    __syncthreads();
}

// ---------------------------------------------------------------------------
// GEMM2 tile (R8-proven): u[128(b) x 128(n)] = e[b][k] * W[k][n],
// K z-split 2 (8192 each). ldmatrix.trans for W. 3-stage, 1 sync/chunk.
// ---------------------------------------------------------------------------
__device__ __forceinline__ void load_g2(uint32_t sbase, int tid,
                                        const __half* Ap, const __half* Bp, int ch) {
#pragma unroll
    for (int t2 = 0; t2 < 2; t2++) {
        int idx = tid + t2 * 512;
        {   // A: 128 rows x 8 segs (K-major)
            int r = idx >> 3, q = idx & 7;
            cpa16(sbase + (uint32_t)(r * ROWB + q * 16),
                  Ap + (size_t)r * Mc + ch * KCH + q * 8);
        }
        {   // B: 64 k-rows x 16 segs (256B rows), XOR swizzle
            int r = idx >> 4, q = idx & 15;
            cpa16(sbase + A2_T + (uint32_t)(r * 256 + ((q ^ (r & 7)) * 16)),
                  Bp + (size_t)(ch * KCH + r) * Nc + q * 8);
        }
    }
}

__device__ void g2_tile(char* smem, int t) {
    const int tid = threadIdx.x;
    const int wid = tid >> 5;
    const int lid = tid & 31;
    const int rw  = wid & 3;
    const int cw  = wid >> 2;
    const uint32_t sb = s2u(smem);

    const int b0 = (t & 1) * 128;
    const int c0 = ((t >> 1) & 31) * 128;
    const int z  = t >> 6;
    const size_t koff = (size_t)z * 8192;

    const __half* Ap = g_fh + (size_t)b0 * Mc + koff;
    const __half* Bp = g_Wh + koff * Nc + c0;
    float* out = &g_vpart[z][0];

    float acc[2][4][4];
#pragma unroll
    for (int i = 0; i < 2; i++)
#pragma unroll
        for (int j = 0; j < 4; j++)
#pragma unroll
            for (int v = 0; v < 4; v++) acc[i][j][v] = 0.0f;

    const int lrow = ((lid >> 3) & 1) * 8 + (lid & 7);
    const int lkb  = (lid >> 4) * 16;
    const int kr   = ((lid >> 4) & 1) * 8 + (lid & 7);
    const int nso  = (lid >> 3) & 1;

    load_g2(sb + 0 * STG2, tid, Ap, Bp, 0);
    CP_COMMIT();
    load_g2(sb + 1 * STG2, tid, Ap, Bp, 1);
    CP_COMMIT();

    for (int ch = 0; ch < 128; ++ch) {
        const uint32_t cur = sb + (uint32_t)(ch % 3) * STG2;
        if (ch + 2 < 128) { CP_WAIT(1); } else { CP_WAIT(0); }
        __syncthreads();
        if (ch + 2 < 128) {
            load_g2(sb + (uint32_t)((ch + 2) % 3) * STG2, tid, Ap, Bp, ch + 2);
            CP_COMMIT();
        }

#pragma unroll
        for (int ks = 0; ks < 4; ++ks) {
            uint32_t aF[2][4];
            uint32_t bF[2][4];
#pragma unroll
            for (int sub = 0; sub < 2; ++sub) {
                uint32_t ra = (uint32_t)((rw * 32 + sub * 16 + lrow) * ROWB
                                         + ks * 32 + lkb);
                ldm4(aF[sub], cur + ra);
            }
#pragma unroll
            for (int cg = 0; cg < 2; ++cg) {
                const int nseg = cw * 4 + cg * 2 + nso;
                uint32_t rb = (uint32_t)((ks * 16 + kr) * 256
                                         + ((nseg ^ (lid & 7)) * 16));
                ldm4t(bF[cg], cur + A2_T + rb);
            }
#pragma unroll
            for (int sub = 0; sub < 2; ++sub)
#pragma unroll
                for (int cg = 0; cg < 2; ++cg)
#pragma unroll
                    for (int hf = 0; hf < 2; ++hf)
                        mma16816(acc[sub][cg * 2 + hf], aF[sub],
                                 bF[cg][hf], bF[cg][hf + 2]);
        }
    }
    __syncthreads();

    const int gr = lid >> 2;
    const int gc = (lid & 3) * 2;
#pragma unroll
    for (int sub = 0; sub < 2; ++sub) {
        const int rbase = b0 + rw * 32 + sub * 16 + gr;
#pragma unroll
        for (int nt = 0; nt < 4; ++nt) {
            const int col = c0 + cw * 32 + nt * 8 + gc;
            *(float2*)(out + (size_t)rbase * Nc + col) =
                make_float2(acc[sub][nt][0], acc[sub][nt][1]);
            *(float2*)(out + (size_t)(rbase + 8) * Nc + col) =
                make_float2(acc[sub][nt][2], acc[sub][nt][3]);
        }
    }
    __syncthreads();
}

// ---------------------------------------------------------------------------
// Persistent kernel: all steps + device-side convergence freeze
// ---------------------------------------------------------------------------
__global__ void __launch_bounds__(512, 1) k_steps(float* __restrict__ state,
                                                  const float* __restrict__ beta_p,
                                                  const float* __restrict__ tau_p,
                                                  int G) {
    extern __shared__ char smem[];
    float* red = (float*)smem;
    const int tid = threadIdx.x;
    const float beta = *beta_p;
    const float invtau = 1.0f / (*tau_p);

    for (int step = 0; step < STEPS; ++step) {
        // GEMM1 + fused exp/rowsum (128 tiles, single wave)
        for (int t = blockIdx.x; t < 128; t += G) g1_tile(smem, t, beta);
        gbar(G);

        // GEMM2 (128 tiles). CTA 0 snapshots + re-zeros row sums.
        if (blockIdx.x == 0 && tid < Bc) {
            g_fsum2[tid] = g_fsum[tid];
            g_fsum[tid] = 0.0f;
        }
        for (int t = blockIdx.x; t < 128; t += G) g2_tile(smem, t);
        gbar(G);

        // Update + norm (v = u / rowsum)
        float sumsq = 0.0f;
        for (int i = blockIdx.x * 512 + tid; i < Bc * Nc; i += G * 512) {
            int b = i >> 12;                        // Nc = 4096
            float v = (g_vpart[0][i] + g_vpart[1][i]) / g_fsum2[b];
            float so = state[i];
            float nv = so + invtau * (v - so);
            float d = nv - so;
            sumsq += d * d;
            state[i] = nv;
            g_sh[i] = __float2half(nv);
        }
        red[tid] = sumsq;
        __syncthreads();
        for (int s = 256; s > 0; s >>= 1) {
            if (tid < s) red[tid] += red[tid + s];
            __syncthreads();
        }
        if (tid == 0) atomicAdd(&g_norm[step], red[0]);
        gbar(G);

        float nrm = *(volatile float*)&g_norm[step];
        if (sqrtf(nrm) <= 1e-3f) break;
        __syncthreads();
    }
}

// ---------------------------------------------------------------------------
// kernel_launch
// ---------------------------------------------------------------------------
extern "C" void kernel_launch(void* const* d_in, const int* in_sizes, int n_in,
                              void* d_out, int out_size) {
    const float* inp  = (const float*)d_in[0];
    const float* W    = (const float*)d_in[1];
    const float* beta = (const float*)d_in[2];
    const float* tau  = (const float*)d_in[3];
    float* state = (float*)d_out;

    int dev = 0;
    cudaGetDevice(&dev);
    cudaDeviceProp props;
    cudaGetDeviceProperties(&props, dev);
    const int G = props.multiProcessorCount;

    cudaFuncSetAttribute(k_steps, cudaFuncAttributeMaxDynamicSharedMemorySize, SMEM_T);

    k_init<<<(Bc * Nc + 255) / 256, 256>>>(inp, state);
    k_convW<<<(size_t)Mc * Nc / 1024, 256>>>(W);
    k_steps<<<G, 512, SMEM_T>>>(state, beta, tau, G);
}

// round 11
// speedup vs baseline: 1.0816x; 1.0024x over previous
#include <cuda_runtime.h>
#include <cuda_fp16.h>
#include <cstdint>
#include <math.h>

// Problem dims (fixed by the dataset)
#define Bc 256
#define Nc 4096
#define Mc 16384
#define STEPS 50

// ---------------------------------------------------------------------------
// Device-global scratch
// ---------------------------------------------------------------------------
__device__ __half g_Wh[(size_t)Mc * Nc];    // W fp16 [m][n] (both GEMMs)
__device__ __half g_sh[(size_t)Bc * Nc];    // state fp16 [b][n]
__device__ __half g_fh[(size_t)Bc * Mc];    // e = exp(beta*h) fp16 [b][m]
__device__ float  g_fsum [Bc];              // row sums (accumulating)
__device__ float  g_fsum2[Bc];              // snapshot read by update
__device__ float  g_vpart[4][(size_t)Bc * Nc];
__device__ float  g_norm[STEPS];

__device__ unsigned g_cnt_bar;
__device__ volatile unsigned g_gen_bar;

// ---------------------------------------------------------------------------
// PTX helpers (sm_80-era, legal on plain sm_103)
// ---------------------------------------------------------------------------
__device__ __forceinline__ uint32_t s2u(const void* p) {
    return (uint32_t)__cvta_generic_to_shared(p);
}
__device__ __forceinline__ void cpa16(uint32_t dst, const void* src) {
    asm volatile("cp.async.cg.shared.global [%0], [%1], 16;" :: "r"(dst), "l"(src));
}
#define CP_COMMIT() asm volatile("cp.async.commit_group;" ::: "memory")
#define CP_WAIT(n)  asm volatile("cp.async.wait_group %0;" :: "n"(n) : "memory")

__device__ __forceinline__ void ldm4(uint32_t* r, uint32_t addr) {
    asm volatile("ldmatrix.sync.aligned.m8n8.x4.shared.b16 {%0,%1,%2,%3}, [%4];"
                 : "=r"(r[0]), "=r"(r[1]), "=r"(r[2]), "=r"(r[3]) : "r"(addr));
}
__device__ __forceinline__ void ldm4t(uint32_t* r, uint32_t addr) {
    asm volatile("ldmatrix.sync.aligned.m8n8.x4.trans.shared.b16 {%0,%1,%2,%3}, [%4];"
                 : "=r"(r[0]), "=r"(r[1]), "=r"(r[2]), "=r"(r[3]) : "r"(addr));
}
__device__ __forceinline__ void mma16816(float* d, const uint32_t* a,
                                         uint32_t b0, uint32_t b1) {
    asm volatile(
        "mma.sync.aligned.m16n8k16.row.col.f32.f16.f16.f32 "
        "{%0,%1,%2,%3}, {%4,%5,%6,%7}, {%8,%9}, {%0,%1,%2,%3};"
        : "+f"(d[0]), "+f"(d[1]), "+f"(d[2]), "+f"(d[3])
        : "r"(a[0]), "r"(a[1]), "r"(a[2]), "r"(a[3]), "r"(b0), "r"(b1));
}

// ---------------------------------------------------------------------------
// Software global barrier (grid == #SMs, 1 CTA/SM -> co-resident)
// ---------------------------------------------------------------------------
__device__ __forceinline__ void gbar(int G) {
    __syncthreads();
    if (threadIdx.x == 0) {
        __threadfence();
        unsigned my = g_gen_bar;
        unsigned old = atomicAdd(&g_cnt_bar, 1u);
        if (old == (unsigned)G - 1u) {
            g_cnt_bar = 0u;
            __threadfence();
            g_gen_bar = my + 1u;
        } else {
            while (g_gen_bar == my) __nanosleep(64);
        }
        __threadfence();
    }
    __syncthreads();
}

// ---------------------------------------------------------------------------
// Init
// ---------------------------------------------------------------------------
__global__ void k_init(const float* __restrict__ inp, float* __restrict__ state) {
    int i = blockIdx.x * blockDim.x + threadIdx.x;
    if (i < Bc * Nc) {
        float x = inp[i];
        state[i] = x;
        g_sh[i] = __float2half(x);
    }
    if (i < STEPS) g_norm[i] = 0.0f;
    if (i < Bc) { g_fsum[i] = 0.0f; g_fsum2[i] = 0.0f; }
}

// ---------------------------------------------------------------------------
// W -> fp16 (elementwise)
// ---------------------------------------------------------------------------
__global__ void __launch_bounds__(256) k_convW(const float* __restrict__ W) {
    size_t i = (size_t)blockIdx.x * 1024 + threadIdx.x * 4;
    float4 v = *(const float4*)(W + i);
    *(__half2*)(g_Wh + i)     = __floats2half2_rn(v.x, v.y);
    *(__half2*)(g_Wh + i + 2) = __floats2half2_rn(v.z, v.w);
}

// ---------------------------------------------------------------------------
// Shared sizes
// ---------------------------------------------------------------------------
#define KCH    64
#define ROWB   144                   // K-major row stride (128B + 16B pad)
// GEMM1: 256(b) x 128(m), 2-stage.  Stage = A(256 rows) + B(128 rows K-major)
#define A1_T   (256 * ROWB)          // 36864 B
#define STG1   (A1_T + 128 * ROWB)   // 55296 B
// GEMM2: 256(b) x 128(n), z-split 4, 2-stage. Stage = A(256 rows) + B(64x256B)
#define STG2   (A1_T + 64 * 256)     // 53248 B
#define SMEM_T (2 * STG1)            // 110592 B (>= 2*STG2)

// ---------------------------------------------------------------------------
// GEMM1 tile: C[256(b) x 128(m)] = state[b][k] * W[m][k], K=4096.
// 16 warps 4(b) x 4(m), warp tile 64x32. 2-stage cp.async, 1 sync/chunk.
// Epilogue: e = __expf(beta*acc) -> g_fh + row-sum atomics into g_fsum.
// ---------------------------------------------------------------------------
__device__ __forceinline__ void load_g1(uint32_t sbase, int tid,
                                        const __half* Bp, int ch) {
#pragma unroll
    for (int t2 = 0; t2 < 4; t2++) {           // A: 256 rows x 8 segs
        int idx = tid + t2 * 512;              // 0..2047
        int r = idx >> 3, q = idx & 7;
        cpa16(sbase + (uint32_t)(r * ROWB + q * 16),
              g_sh + (size_t)r * Nc + ch * KCH + q * 8);
    }
#pragma unroll
    for (int t2 = 0; t2 < 2; t2++) {           // B: 128 rows x 8 segs
        int idx = tid + t2 * 512;              // 0..1023
        int r = idx >> 3, q = idx & 7;
        cpa16(sbase + A1_T + (uint32_t)(r * ROWB + q * 16),
              Bp + (size_t)r * Nc + ch * KCH + q * 8);
    }
}

__device__ void g1_tile(char* smem, int t, float beta) {
    const int tid = threadIdx.x;
    const int wid = tid >> 5;
    const int lid = tid & 31;
    const int rw  = wid & 3;            // warp b-row: 64 rows
    const int cw  = wid >> 2;           // warp m-col: 32 cols
    const uint32_t sb = s2u(smem);

    const int c0 = t * 128;
    const __half* Bp = g_Wh + (size_t)c0 * Nc;

    float acc[4][4][4];
#pragma unroll
    for (int i = 0; i < 4; i++)
#pragma unroll
        for (int j = 0; j < 4; j++)
#pragma unroll
            for (int v = 0; v < 4; v++) acc[i][j][v] = 0.0f;

    const int lrow = ((lid >> 3) & 1) * 8 + (lid & 7);
    const int lkb  = (lid >> 4) * 16;

    load_g1(sb, tid, Bp, 0);
    CP_COMMIT();

    for (int ch = 0; ch < 64; ++ch) {
        const uint32_t cur = sb + (uint32_t)(ch & 1) * STG1;
        CP_WAIT(0);
        __syncthreads();
        if (ch + 1 < 64) {
            load_g1(sb + (uint32_t)((ch + 1) & 1) * STG1, tid, Bp, ch + 1);
            CP_COMMIT();
        }

#pragma unroll
        for (int ks = 0; ks < 4; ++ks) {
            uint32_t aF[4][4];
            uint32_t bF[2][4];
#pragma unroll
            for (int sub = 0; sub < 4; ++sub) {
                uint32_t ra = (uint32_t)((rw * 64 + sub * 16 + lrow) * ROWB
                                         + ks * 32 + lkb);
                ldm4(aF[sub], cur + ra);
            }
#pragma unroll
            for (int cg = 0; cg < 2; ++cg) {
                uint32_t rb = (uint32_t)((cw * 32 + cg * 16 + lrow) * ROWB
                                         + ks * 32 + lkb);
                ldm4(bF[cg], cur + A1_T + rb);
            }
#pragma unroll
            for (int sub = 0; sub < 4; ++sub)
#pragma unroll
                for (int cg = 0; cg < 2; ++cg)
#pragma unroll
                    for (int hf = 0; hf < 2; ++hf)
                        mma16816(acc[sub][cg * 2 + hf], aF[sub],
                                 bF[cg][hf], bF[cg][hf + 2]);
        }
    }
    __syncthreads();   // stages dead; smem reusable

    // Epilogue: e = __expf(beta*h) -> fp16 g_fh; row sums -> g_fsum
    const int gr = lid >> 2;
    const int gc = (lid & 3) * 2;
    float* rsum = (float*)smem;
    if (tid < 256) rsum[tid] = 0.0f;
    __syncthreads();

#pragma unroll
    for (int sub = 0; sub < 4; ++sub) {
        const int rbase = rw * 64 + sub * 16 + gr;
        float s0 = 0.0f, s1 = 0.0f;
#pragma unroll
        for (int nt = 0; nt < 4; ++nt) {
            float e0 = __expf(beta * acc[sub][nt][0]);
            float e1 = __expf(beta * acc[sub][nt][1]);
            float e2 = __expf(beta * acc[sub][nt][2]);
            float e3 = __expf(beta * acc[sub][nt][3]);
            const int col = c0 + cw * 32 + nt * 8 + gc;
            *(__half2*)(g_fh + (size_t)rbase * Mc + col) =
                __floats2half2_rn(e0, e1);
            *(__half2*)(g_fh + (size_t)(rbase + 8) * Mc + col) =
                __floats2half2_rn(e2, e3);
            s0 += e0 + e1;
            s1 += e2 + e3;
        }
        s0 += __shfl_xor_sync(0xFFFFFFFF, s0, 1);
        s0 += __shfl_xor_sync(0xFFFFFFFF, s0, 2);
        s1 += __shfl_xor_sync(0xFFFFFFFF, s1, 1);
        s1 += __shfl_xor_sync(0xFFFFFFFF, s1, 2);
        if ((lid & 3) == 0) {
            atomicAdd(&rsum[rbase], s0);
            atomicAdd(&rsum[rbase + 8], s1);
        }
    }
    __syncthreads();
    if (tid < 256) atomicAdd(&g_fsum[tid], rsum[tid]);
    __syncthreads();
}

// ---------------------------------------------------------------------------
// GEMM2 tile: u[256(b) x 128(n)] = e[b][k] * W[k][n], K z-split 4 (4096 each).
// 16 warps 4(b) x 4(n), warp tile 64x32. ldmatrix.trans for W.
// 2-stage cp.async, 1 sync/chunk. Partial to g_vpart[z].
// ---------------------------------------------------------------------------
__device__ __forceinline__ void load_g2(uint32_t sbase, int tid,
                                        const __half* Ap, const __half* Bp, int ch) {
#pragma unroll
    for (int t2 = 0; t2 < 4; t2++) {           // A: 256 rows x 8 segs (K-major)
        int idx = tid + t2 * 512;
        int r = idx >> 3, q = idx & 7;
        cpa16(sbase + (uint32_t)(r * ROWB + q * 16),
              Ap + (size_t)r * Mc + ch * KCH + q * 8);
    }
#pragma unroll
    for (int t2 = 0; t2 < 2; t2++) {           // B: 64 k-rows x 16 segs, XOR swizzle
        int idx = tid + t2 * 512;
        int r = idx >> 4, q = idx & 15;
        cpa16(sbase + A1_T + (uint32_t)(r * 256 + ((q ^ (r & 7)) * 16)),
              Bp + (size_t)(ch * KCH + r) * Nc + q * 8);
    }
}

__device__ void g2_tile(char* smem, int t) {
    const int tid = threadIdx.x;
    const int wid = tid >> 5;
    const int lid = tid & 31;
    const int rw  = wid & 3;            // warp b-row: 64 rows
    const int cw  = wid >> 2;           // warp n-col: 32 cols
    const uint32_t sb = s2u(smem);

    const int z  = t >> 5;
    const int c0 = (t & 31) * 128;
    const size_t koff = (size_t)z * 4096;

    const __half* Ap = g_fh + koff;
    const __half* Bp = g_Wh + koff * Nc + c0;
    float* out = &g_vpart[z][0];

    float acc[4][4][4];
#pragma unroll
    for (int i = 0; i < 4; i++)
#pragma unroll
        for (int j = 0; j < 4; j++)
#pragma unroll
            for (int v = 0; v < 4; v++) acc[i][j][v] = 0.0f;

    const int lrow = ((lid >> 3) & 1) * 8 + (lid & 7);
    const int lkb  = (lid >> 4) * 16;
    const int kr   = ((lid >> 4) & 1) * 8 + (lid & 7);
    const int nso  = (lid >> 3) & 1;

    load_g2(sb, tid, Ap, Bp, 0);
    CP_COMMIT();

    for (int ch = 0; ch < 64; ++ch) {
        const uint32_t cur = sb + (uint32_t)(ch & 1) * STG2;
        CP_WAIT(0);
        __syncthreads();
        if (ch + 1 < 64) {
            load_g2(sb + (uint32_t)((ch + 1) & 1) * STG2, tid, Ap, Bp, ch + 1);
            CP_COMMIT();
        }

#pragma unroll
        for (int ks = 0; ks < 4; ++ks) {
            uint32_t aF[4][4];
            uint32_t bF[2][4];
#pragma unroll
            for (int sub = 0; sub < 4; ++sub) {
                uint32_t ra = (uint32_t)((rw * 64 + sub * 16 + lrow) * ROWB
                                         + ks * 32 + lkb);
                ldm4(aF[sub], cur + ra);
            }
#pragma unroll
            for (int cg = 0; cg < 2; ++cg) {
                const int nseg = cw * 4 + cg * 2 + nso;
                uint32_t rb = (uint32_t)((ks * 16 + kr) * 256
                                         + ((nseg ^ (lid & 7)) * 16));
                ldm4t(bF[cg], cur + A1_T + rb);
            }
#pragma unroll
            for (int sub = 0; sub < 4; ++sub)
#pragma unroll
                for (int cg = 0; cg < 2; ++cg)
#pragma unroll
                    for (int hf = 0; hf < 2; ++hf)
                        mma16816(acc[sub][cg * 2 + hf], aF[sub],
                                 bF[cg][hf], bF[cg][hf + 2]);
        }
    }
    __syncthreads();

    const int gr = lid >> 2;
    const int gc = (lid & 3) * 2;
#pragma unroll
    for (int sub = 0; sub < 4; ++sub) {
        const int rbase = rw * 64 + sub * 16 + gr;
#pragma unroll
        for (int nt = 0; nt < 4; ++nt) {
            const int col = c0 + cw * 32 + nt * 8 + gc;
            *(float2*)(out + (size_t)rbase * Nc + col) =
                make_float2(acc[sub][nt][0], acc[sub][nt][1]);
            *(float2*)(out + (size_t)(rbase + 8) * Nc + col) =
                make_float2(acc[sub][nt][2], acc[sub][nt][3]);
        }
    }
    __syncthreads();
}

// ---------------------------------------------------------------------------
// Persistent kernel: all steps + device-side convergence freeze
// ---------------------------------------------------------------------------
__global__ void __launch_bounds__(512, 1) k_steps(float* __restrict__ state,
                                                  const float* __restrict__ beta_p,
                                                  const float* __restrict__ tau_p,
                                                  int G) {
    extern __shared__ char smem[];
    float* red = (float*)smem;
    const int tid = threadIdx.x;
    const float beta = *beta_p;
    const float invtau = 1.0f / (*tau_p);

    for (int step = 0; step < STEPS; ++step) {
        // GEMM1 + fused exp/rowsum (128 tiles, single wave)
        for (int t = blockIdx.x; t < 128; t += G) g1_tile(smem, t, beta);
        gbar(G);

        // GEMM2 (128 tiles, z-split 4). CTA 0 snapshots + re-zeros row sums.
        if (blockIdx.x == 0 && tid < Bc) {
            g_fsum2[tid] = g_fsum[tid];
            g_fsum[tid] = 0.0f;
        }
        for (int t = blockIdx.x; t < 128; t += G) g2_tile(smem, t);
        gbar(G);

        // Update + norm (v = (sum of 4 partials) / rowsum)
        float sumsq = 0.0f;
        for (int i = blockIdx.x * 512 + tid; i < Bc * Nc; i += G * 512) {
            int b = i >> 12;                        // Nc = 4096
            float v = (g_vpart[0][i] + g_vpart[1][i] +
                       g_vpart[2][i] + g_vpart[3][i]) / g_fsum2[b];
            float so = state[i];
            float nv = so + invtau * (v - so);
            float d = nv - so;
            sumsq += d * d;
            state[i] = nv;
            g_sh[i] = __float2half(nv);
        }
        red[tid] = sumsq;
        __syncthreads();
        for (int s = 256; s > 0; s >>= 1) {
            if (tid < s) red[tid] += red[tid + s];
            __syncthreads();
        }
        if (tid == 0) atomicAdd(&g_norm[step], red[0]);
        gbar(G);

        float nrm = *(volatile float*)&g_norm[step];
        if (sqrtf(nrm) <= 1e-3f) break;
        __syncthreads();
    }
}

// ---------------------------------------------------------------------------
// kernel_launch
// ---------------------------------------------------------------------------
extern "C" void kernel_launch(void* const* d_in, const int* in_sizes, int n_in,
                              void* d_out, int out_size) {
    const float* inp  = (const float*)d_in[0];
    const float* W    = (const float*)d_in[1];
    const float* beta = (const float*)d_in[2];
    const float* tau  = (const float*)d_in[3];
    float* state = (float*)d_out;

    int dev = 0;
    cudaGetDevice(&dev);
    cudaDeviceProp props;
    cudaGetDeviceProperties(&props, dev);
    const int G = props.multiProcessorCount;

    cudaFuncSetAttribute(k_steps, cudaFuncAttributeMaxDynamicSharedMemorySize, SMEM_T);

    k_init<<<(Bc * Nc + 255) / 256, 256>>>(inp, state);
    k_convW<<<(size_t)Mc * Nc / 1024, 256>>>(W);
    k_steps<<<G, 512, SMEM_T>>>(state, beta, tau, G);
}